// round 8
// baseline (speedup 1.0000x reference)
#include <cuda_runtime.h>
#include <math.h>

#define GRID_RES 256
#define CELLSZ   0.015f
#define NS       64
#define MIN_BETA 0.015f

// Extract corners (dx,dy,0) and (dx,dy,1) channels 0..3 from a 12-float aligned
// window w[0..11] where corner0 ch j = w[k+j], corner1 ch j = w[k+5+j], k in [0,3].
// 2-level select tree keeps everything in registers (no dynamic indexing).
__device__ __forceinline__ void pick_pair(const float w[12], int k,
                                          float o0[4], float o1[4]) {
    const bool s2 = (k & 2) != 0;
    const bool s1 = (k & 1) != 0;
    float t[10];
    #pragma unroll
    for (int j = 0; j < 10; j++) t[j] = s2 ? w[j + 2] : w[j];
    #pragma unroll
    for (int j = 0; j < 4; j++) o0[j] = s1 ? t[j + 1] : t[j];
    #pragma unroll
    for (int j = 0; j < 4; j++) o1[j] = s1 ? t[j + 6] : t[j + 5];
}

// 128 threads = 4 warps = 2 rays per block; thread-per-sample.
__global__ void __launch_bounds__(128, 6)
plainvoxels_render_kernel(
    const float* __restrict__ grid,        // [256,256,256,5]
    const float* __restrict__ beta,        // [1]
    const float* __restrict__ rays_o,      // [N,3]
    const float* __restrict__ rays_d,      // [N,3]
    const float* __restrict__ rays_d_norm, // [N,1]
    const float* __restrict__ nearp,       // [1]
    const float* __restrict__ farp,        // [1]
    float* __restrict__ out_rgb,     // [N,3]
    float* __restrict__ out_depth,   // [N,1]
    float* __restrict__ out_normals, // [N,3]
    float* __restrict__ out_acc,     // [N,1]
    float* __restrict__ out_grads,   // [N*NS,3]
    float* __restrict__ out_near,    // [N,1]
    float* __restrict__ out_far,     // [N,1]
    int N)
{
    __shared__ float warp_tot[4];
    __shared__ float red[4][8];

    const int tid  = threadIdx.x;
    const int warp = tid >> 5;
    const int lane = tid & 31;
    const int s    = tid & 63;
    const int nray = blockIdx.x * 2 + (tid >> 6);
    const bool valid = (nray < N);
    const int n = valid ? nray : (N - 1);

    const float ORIGIN = __fmul_rn(__fmul_rn(-0.5f, (float)GRID_RES), CELLSZ);

    const float ox = rays_o[3*n+0], oy = rays_o[3*n+1], oz = rays_o[3*n+2];
    const float dx = rays_d[3*n+0], dy = rays_d[3*n+1], dz = rays_d[3*n+2];
    const float nr = nearp[0], fr = farp[0];
    const float dt = __fdiv_rn(__fsub_rn(fr, nr), (float)NS);
    const float beta_eff = MIN_BETA + fabsf(beta[0]);
    const float inv_beta = 1.0f / beta_eff;

    // exact reference rounding
    const float t_n   = __fadd_rn(nr, __fmul_rn((float)s, dt));
    const float t_f   = __fadd_rn(t_n, dt);
    const float t_mid = __fmul_rn(0.5f, __fadd_rn(t_n, t_f));
    const float px = __fadd_rn(ox, __fmul_rn(t_mid, dx));
    const float py = __fadd_rn(oy, __fmul_rn(t_mid, dy));
    const float pz = __fadd_rn(oz, __fmul_rn(t_mid, dz));

    const float ux = __fdiv_rn(__fsub_rn(px, ORIGIN), CELLSZ);
    const float uy = __fdiv_rn(__fsub_rn(py, ORIGIN), CELLSZ);
    const float uz = __fdiv_rn(__fsub_rn(pz, ORIGIN), CELLSZ);

    const bool mask = (ux >= 0.0f) && (ux <= (float)(GRID_RES-1)) &&
                      (uy >= 0.0f) && (uy <= (float)(GRID_RES-1)) &&
                      (uz >= 0.0f) && (uz <= (float)(GRID_RES-1));

    const int ix = min(max((int)floorf(ux), 0), GRID_RES - 2);
    const int iy = min(max((int)floorf(uy), 0), GRID_RES - 2);
    const int iz = min(max((int)floorf(uz), 0), GRID_RES - 2);
    const float fx = __fsub_rn(ux, (float)ix);
    const float fy = __fsub_rn(uy, (float)iy);
    const float fz = __fsub_rn(uz, (float)iz);

    const int base = ((ix * GRID_RES + iy) * GRID_RES + iz) * 5;
    const int OX = GRID_RES * GRID_RES * 5;
    const int OY = GRID_RES * 5;

    // element indices of the 4 (x,y) pairs (dz=0 corner)
    const int e00 = base;
    const int e01 = base + OY;
    const int e10 = base + OX;
    const int e11 = base + OX + OY;

    // 3x LDG.128 per pair from 16B-aligned window [e & ~3, e & ~3 + 12)
    const float4* q00 = (const float4*)(grid + (e00 & ~3));
    const float4* q01 = (const float4*)(grid + (e01 & ~3));
    const float4* q10 = (const float4*)(grid + (e10 & ~3));
    const float4* q11 = (const float4*)(grid + (e11 & ~3));

    float4 a0 = __ldg(q00 + 0), b0 = __ldg(q00 + 1), c0 = __ldg(q00 + 2);
    float4 a1 = __ldg(q01 + 0), b1 = __ldg(q01 + 1), c1 = __ldg(q01 + 2);
    float4 a2 = __ldg(q10 + 0), b2 = __ldg(q10 + 1), c2 = __ldg(q10 + 2);
    float4 a3 = __ldg(q11 + 0), b3 = __ldg(q11 + 1), c3 = __ldg(q11 + 2);

    // v[c][ch], corner bit2=dx, bit1=dy, bit0=dz
    float v[8][4];
    {
        float w[12] = {a0.x,a0.y,a0.z,a0.w, b0.x,b0.y,b0.z,b0.w, c0.x,c0.y,c0.z,c0.w};
        pick_pair(w, e00 & 3, v[0], v[1]);
    }
    {
        float w[12] = {a1.x,a1.y,a1.z,a1.w, b1.x,b1.y,b1.z,b1.w, c1.x,c1.y,c1.z,c1.w};
        pick_pair(w, e01 & 3, v[2], v[3]);
    }
    {
        float w[12] = {a2.x,a2.y,a2.z,a2.w, b2.x,b2.y,b2.z,b2.w, c2.x,c2.y,c2.z,c2.w};
        pick_pair(w, e10 & 3, v[4], v[5]);
    }
    {
        float w[12] = {a3.x,a3.y,a3.z,a3.w, b3.x,b3.y,b3.z,b3.w, c3.x,c3.y,c3.z,c3.w};
        pick_pair(w, e11 & 3, v[6], v[7]);
    }

    const float gx = 1.0f - fx, gy = 1.0f - fy, gz = 1.0f - fz;

    float feat[4];
    #pragma unroll
    for (int ch = 0; ch < 4; ch++) {
        const float c00 = v[0][ch] * gx + v[4][ch] * fx;
        const float c10 = v[2][ch] * gx + v[6][ch] * fx;
        const float c01 = v[1][ch] * gx + v[5][ch] * fx;
        const float c11 = v[3][ch] * gx + v[7][ch] * fx;
        const float cc0 = c00 * gy + c10 * fy;
        const float cc1 = c01 * gy + c11 * fy;
        feat[ch] = cc0 * gz + cc1 * fz;
    }
    const float sdf = feat[0];

    // analytic gradient of trilinear sdf
    const float dfx = ((v[4][0]-v[0][0])*gy + (v[6][0]-v[2][0])*fy) * gz
                    + ((v[5][0]-v[1][0])*gy + (v[7][0]-v[3][0])*fy) * fz;
    const float dfy = ((v[2][0]-v[0][0])*gx + (v[6][0]-v[4][0])*fx) * gz
                    + ((v[3][0]-v[1][0])*gx + (v[7][0]-v[5][0])*fx) * fz;
    const float dfz = ((v[1][0]-v[0][0])*gx + (v[5][0]-v[4][0])*fx) * gy
                    + ((v[3][0]-v[2][0])*gx + (v[7][0]-v[6][0])*fx) * fy;
    const float grx = __fdiv_rn(dfx, CELLSZ);
    const float gry = __fdiv_rn(dfy, CELLSZ);
    const float grz = __fdiv_rn(dfz, CELLSZ);

    if (valid) {
        const int m = n * NS + s;
        out_grads[3*m+0] = grx;
        out_grads[3*m+1] = gry;
        out_grads[3*m+2] = grz;
    }

    // unit normal (IEEE ops)
    const float gl = __fsqrt_rn(__fadd_rn(__fadd_rn(__fmul_rn(grx,grx),
                        __fmul_rn(gry,gry)), __fmul_rn(grz,grz)));
    const float den = fmaxf(gl, 1e-12f);
    const float nx = __fdiv_rn(grx, den);
    const float ny = __fdiv_rn(gry, den);
    const float nz = __fdiv_rn(grz, den);

    // Laplace CDF density
    const float sgn = (sdf > 0.0f) ? 1.0f : ((sdf < 0.0f) ? -1.0f : 0.0f);
    float sigma = inv_beta * (0.5f + 0.5f * sgn * expm1f(-fabsf(sdf) * inv_beta));
    if (!mask) sigma = 0.0f;
    const float tau = sigma * dt;

    // ---- 2-warp exclusive prefix of tau over 64 samples ----
    float x = tau;
    #pragma unroll
    for (int o = 1; o < 32; o <<= 1) {
        float y = __shfl_up_sync(0xFFFFFFFFu, x, o);
        if (lane >= o) x += y;
    }
    if (lane == 31) warp_tot[warp] = x;
    __syncthreads();
    float excl = x - tau;
    if (s >= 32) excl += warp_tot[warp - 1];

    const float T = expf(-excl);
    const float a = -expm1f(-tau);
    const float w = T * a;

    // ---- composite ----
    float acc[8];
    acc[0] = w * feat[1];
    acc[1] = w * feat[2];
    acc[2] = w * feat[3];
    acc[3] = w * nx;
    acc[4] = w * ny;
    acc[5] = w * nz;
    acc[6] = w * t_mid;
    acc[7] = w;

    #pragma unroll
    for (int o = 16; o >= 1; o >>= 1) {
        #pragma unroll
        for (int k = 0; k < 8; k++)
            acc[k] += __shfl_xor_sync(0xFFFFFFFFu, acc[k], o);
    }
    if (lane == 0) {
        #pragma unroll
        for (int k = 0; k < 8; k++) red[warp][k] = acc[k];
    }
    __syncthreads();

    if ((tid & 63) == 0 && valid) {
        float r0 = red[warp][0] + red[warp+1][0];
        float r1 = red[warp][1] + red[warp+1][1];
        float r2 = red[warp][2] + red[warp+1][2];
        float r3 = red[warp][3] + red[warp+1][3];
        float r4 = red[warp][4] + red[warp+1][4];
        float r5 = red[warp][5] + red[warp+1][5];
        float r6 = red[warp][6] + red[warp+1][6];
        float r7 = red[warp][7] + red[warp+1][7];
        const float rdn = rays_d_norm[n];
        out_rgb[3*n+0] = r0;
        out_rgb[3*n+1] = r1;
        out_rgb[3*n+2] = r2;
        out_depth[n]   = __fdiv_rn(r6, rdn);
        out_normals[3*n+0] = r3;
        out_normals[3*n+1] = r4;
        out_normals[3*n+2] = r5;
        out_acc[n]     = r7;
        out_near[n]    = __fdiv_rn(nr, rdn);
        out_far[n]     = __fdiv_rn(fr, rdn);
    }
}

extern "C" void kernel_launch(void* const* d_in, const int* in_sizes, int n_in,
                              void* d_out, int out_size) {
    const float* grid        = (const float*)d_in[0];
    const float* beta        = (const float*)d_in[1];
    const float* rays_o      = (const float*)d_in[2];
    const float* rays_d      = (const float*)d_in[3];
    const float* rays_d_norm = (const float*)d_in[4];
    const float* nearp       = (const float*)d_in[5];
    const float* farp        = (const float*)d_in[6];

    const int N = in_sizes[2] / 3;

    float* out = (float*)d_out;
    float* out_rgb     = out;
    float* out_depth   = out_rgb + (size_t)3 * N;
    float* out_normals = out_depth + N;
    float* out_acc     = out_normals + (size_t)3*N;
    float* out_grads   = out_acc + N;
    float* out_near    = out_grads + (size_t)3 * N * NS;
    float* out_far     = out_near + N;

    const int threads = 128;
    const int blocks  = (N * NS + threads - 1) / threads;
    plainvoxels_render_kernel<<<blocks, threads>>>(
        grid, beta, rays_o, rays_d, rays_d_norm, nearp, farp,
        out_rgb, out_depth, out_normals, out_acc, out_grads, out_near, out_far, N);
}

// round 9
// speedup vs baseline: 1.5768x; 1.5768x over previous
#include <cuda_runtime.h>
#include <math.h>

#define GRID_RES 256
#define CELLSZ   0.015f
#define NS       64
#define MIN_BETA 0.015f

// 128 threads = 4 warps = 2 rays per block; thread-per-sample.
// 8 blocks/SM min -> 64-reg cap so the 20 LDG.64s stay front-batched at occ 50%.
__global__ void __launch_bounds__(128, 8)
plainvoxels_render_kernel(
    const float* __restrict__ grid,        // [256,256,256,5]
    const float* __restrict__ beta,        // [1]
    const float* __restrict__ rays_o,      // [N,3]
    const float* __restrict__ rays_d,      // [N,3]
    const float* __restrict__ rays_d_norm, // [N,1]
    const float* __restrict__ nearp,       // [1]
    const float* __restrict__ farp,        // [1]
    float* __restrict__ out_rgb,     // [N,3]
    float* __restrict__ out_depth,   // [N,1]
    float* __restrict__ out_normals, // [N,3]
    float* __restrict__ out_acc,     // [N,1]
    float* __restrict__ out_grads,   // [N*NS,3]
    float* __restrict__ out_near,    // [N,1]
    float* __restrict__ out_far,     // [N,1]
    int N)
{
    __shared__ float warp_tot[4];
    __shared__ float red[4][8];

    const int tid  = threadIdx.x;
    const int warp = tid >> 5;
    const int lane = tid & 31;
    const int s    = tid & 63;
    const int nray = blockIdx.x * 2 + (tid >> 6);
    const bool valid = (nray < N);
    const int n = valid ? nray : (N - 1);

    const float ORIGIN = __fmul_rn(__fmul_rn(-0.5f, (float)GRID_RES), CELLSZ);

    const float ox = rays_o[3*n+0], oy = rays_o[3*n+1], oz = rays_o[3*n+2];
    const float dx = rays_d[3*n+0], dy = rays_d[3*n+1], dz = rays_d[3*n+2];
    const float nr = nearp[0], fr = farp[0];
    const float dt = __fdiv_rn(__fsub_rn(fr, nr), (float)NS);
    const float beta_eff = MIN_BETA + fabsf(beta[0]);
    const float inv_beta = 1.0f / beta_eff;

    // exact reference rounding (floor/index path must be bit-exact)
    const float t_n   = __fadd_rn(nr, __fmul_rn((float)s, dt));
    const float t_f   = __fadd_rn(t_n, dt);
    const float t_mid = __fmul_rn(0.5f, __fadd_rn(t_n, t_f));
    const float px = __fadd_rn(ox, __fmul_rn(t_mid, dx));
    const float py = __fadd_rn(oy, __fmul_rn(t_mid, dy));
    const float pz = __fadd_rn(oz, __fmul_rn(t_mid, dz));

    const float ux = __fdiv_rn(__fsub_rn(px, ORIGIN), CELLSZ);
    const float uy = __fdiv_rn(__fsub_rn(py, ORIGIN), CELLSZ);
    const float uz = __fdiv_rn(__fsub_rn(pz, ORIGIN), CELLSZ);

    const bool mask = (ux >= 0.0f) && (ux <= (float)(GRID_RES-1)) &&
                      (uy >= 0.0f) && (uy <= (float)(GRID_RES-1)) &&
                      (uz >= 0.0f) && (uz <= (float)(GRID_RES-1));

    const int ix = min(max((int)floorf(ux), 0), GRID_RES - 2);
    const int iy = min(max((int)floorf(uy), 0), GRID_RES - 2);
    const int iz = min(max((int)floorf(uz), 0), GRID_RES - 2);
    const float fx = __fsub_rn(ux, (float)ix);
    const float fy = __fsub_rn(uy, (float)iy);
    const float fz = __fsub_rn(uz, (float)iz);

    const int base = ((ix * GRID_RES + iy) * GRID_RES + iz) * 5;
    const int OX = GRID_RES * GRID_RES * 5;   // 327680 (even)
    const int OY = GRID_RES * 5;              // 1280   (even)

    // z-pair windows: pair p=(dx<<1|dy) needs floats [e_p, e_p+9), e_p = base + dx*OX + dy*OY.
    // OX, OY even => e_p parity == base parity for all pairs: one select bit.
    const int kpar = base & 1;
    const float2* q0 = (const float2*)(grid + ((base)            & ~1));
    const float2* q1 = (const float2*)(grid + ((base + OY)       & ~1));
    const float2* q2 = (const float2*)(grid + ((base + OX)       & ~1));
    const float2* q3 = (const float2*)(grid + ((base + OX + OY)  & ~1));

    // Front-batch ALL 20 LDG.64s (40 dest regs) before any FP consumption.
    float2 W[4][5];
    #pragma unroll
    for (int j = 0; j < 5; j++) W[0][j] = __ldg(q0 + j);
    #pragma unroll
    for (int j = 0; j < 5; j++) W[1][j] = __ldg(q1 + j);
    #pragma unroll
    for (int j = 0; j < 5; j++) W[2][j] = __ldg(q2 + j);
    #pragma unroll
    for (int j = 0; j < 5; j++) W[3][j] = __ldg(q3 + j);

    const float gx = 1.0f - fx, gy = 1.0f - fy, gz = 1.0f - fz;
    const bool ksel = (kpar != 0);

    // Accumulate trilinear + gradient pair-by-pair so window regs die early.
    float feat0 = 0.f, feat1 = 0.f, feat2 = 0.f, feat3 = 0.f;
    float dfx = 0.f, dfy = 0.f, dfzv = 0.f;

    #pragma unroll
    for (int p = 0; p < 4; p++) {
        float w[10];
        w[0] = W[p][0].x; w[1] = W[p][0].y;
        w[2] = W[p][1].x; w[3] = W[p][1].y;
        w[4] = W[p][2].x; w[5] = W[p][2].y;
        w[6] = W[p][3].x; w[7] = W[p][3].y;
        w[8] = W[p][4].x; w[9] = W[p][4].y;

        // corner (dx,dy,0) chans = w[k..k+3], corner (dx,dy,1) chans = w[k+5..k+8]
        float v0[4], v1[4];
        #pragma unroll
        for (int j = 0; j < 4; j++) v0[j] = ksel ? w[j + 1] : w[j];
        #pragma unroll
        for (int j = 0; j < 4; j++) v1[j] = ksel ? w[j + 6] : w[j + 5];

        const float wx  = (p & 2) ? fx : gx;
        const float wy  = (p & 1) ? fy : gy;
        const float wxy = wx * wy;

        const float zb0 = v0[0] * gz + v1[0] * fz;
        const float zb1 = v0[1] * gz + v1[1] * fz;
        const float zb2 = v0[2] * gz + v1[2] * fz;
        const float zb3 = v0[3] * gz + v1[3] * fz;

        feat0 += zb0 * wxy;
        feat1 += zb1 * wxy;
        feat2 += zb2 * wxy;
        feat3 += zb3 * wxy;
        dfzv  += (v1[0] - v0[0]) * wxy;
        dfx   += (p & 2) ? (zb0 * wy) : (-zb0 * wy);
        dfy   += (p & 1) ? (zb0 * wx) : (-zb0 * wx);
    }

    const float sdf = feat0;
    const float grx = __fdiv_rn(dfx,  CELLSZ);
    const float gry = __fdiv_rn(dfy,  CELLSZ);
    const float grz = __fdiv_rn(dfzv, CELLSZ);

    if (valid) {
        const int m = n * NS + s;
        out_grads[3*m+0] = grx;
        out_grads[3*m+1] = gry;
        out_grads[3*m+2] = grz;
    }

    // unit normal (IEEE ops)
    const float gl = __fsqrt_rn(__fadd_rn(__fadd_rn(__fmul_rn(grx,grx),
                        __fmul_rn(gry,gry)), __fmul_rn(grz,grz)));
    const float den = fmaxf(gl, 1e-12f);
    const float nx = __fdiv_rn(grx, den);
    const float ny = __fdiv_rn(gry, den);
    const float nz = __fdiv_rn(grz, den);

    // Laplace CDF density
    const float sgn = (sdf > 0.0f) ? 1.0f : ((sdf < 0.0f) ? -1.0f : 0.0f);
    float sigma = inv_beta * (0.5f + 0.5f * sgn * expm1f(-fabsf(sdf) * inv_beta));
    if (!mask) sigma = 0.0f;
    const float tau = sigma * dt;

    // ---- 2-warp exclusive prefix of tau over 64 samples ----
    float x = tau;
    #pragma unroll
    for (int o = 1; o < 32; o <<= 1) {
        float y = __shfl_up_sync(0xFFFFFFFFu, x, o);
        if (lane >= o) x += y;
    }
    if (lane == 31) warp_tot[warp] = x;
    __syncthreads();
    float excl = x - tau;
    if (s >= 32) excl += warp_tot[warp - 1];

    const float T = expf(-excl);
    const float a = -expm1f(-tau);
    const float w = T * a;

    // ---- composite ----
    float acc[8];
    acc[0] = w * feat1;
    acc[1] = w * feat2;
    acc[2] = w * feat3;
    acc[3] = w * nx;
    acc[4] = w * ny;
    acc[5] = w * nz;
    acc[6] = w * t_mid;
    acc[7] = w;

    #pragma unroll
    for (int o = 16; o >= 1; o >>= 1) {
        #pragma unroll
        for (int k = 0; k < 8; k++)
            acc[k] += __shfl_xor_sync(0xFFFFFFFFu, acc[k], o);
    }
    if (lane == 0) {
        #pragma unroll
        for (int k = 0; k < 8; k++) red[warp][k] = acc[k];
    }
    __syncthreads();

    if ((tid & 63) == 0 && valid) {
        float r0 = red[warp][0] + red[warp+1][0];
        float r1 = red[warp][1] + red[warp+1][1];
        float r2 = red[warp][2] + red[warp+1][2];
        float r3 = red[warp][3] + red[warp+1][3];
        float r4 = red[warp][4] + red[warp+1][4];
        float r5 = red[warp][5] + red[warp+1][5];
        float r6 = red[warp][6] + red[warp+1][6];
        float r7 = red[warp][7] + red[warp+1][7];
        const float rdn = rays_d_norm[n];
        out_rgb[3*n+0] = r0;
        out_rgb[3*n+1] = r1;
        out_rgb[3*n+2] = r2;
        out_depth[n]   = __fdiv_rn(r6, rdn);
        out_normals[3*n+0] = r3;
        out_normals[3*n+1] = r4;
        out_normals[3*n+2] = r5;
        out_acc[n]     = r7;
        out_near[n]    = __fdiv_rn(nr, rdn);
        out_far[n]     = __fdiv_rn(fr, rdn);
    }
}

extern "C" void kernel_launch(void* const* d_in, const int* in_sizes, int n_in,
                              void* d_out, int out_size) {
    const float* grid        = (const float*)d_in[0];
    const float* beta        = (const float*)d_in[1];
    const float* rays_o      = (const float*)d_in[2];
    const float* rays_d      = (const float*)d_in[3];
    const float* rays_d_norm = (const float*)d_in[4];
    const float* nearp       = (const float*)d_in[5];
    const float* farp        = (const float*)d_in[6];

    const int N = in_sizes[2] / 3;

    float* out = (float*)d_out;
    float* out_rgb     = out;
    float* out_depth   = out_rgb + (size_t)3 * N;
    float* out_normals = out_depth + N;
    float* out_acc     = out_normals + (size_t)3*N;
    float* out_grads   = out_acc + N;
    float* out_near    = out_grads + (size_t)3 * N * NS;
    float* out_far     = out_near + N;

    const int threads = 128;
    const int blocks  = (N * NS + threads - 1) / threads;
    plainvoxels_render_kernel<<<blocks, threads>>>(
        grid, beta, rays_o, rays_d, rays_d_norm, nearp, farp,
        out_rgb, out_depth, out_normals, out_acc, out_grads, out_near, out_far, N);
}